// round 4
// baseline (speedup 1.0000x reference)
#include <cuda_runtime.h>
#include <math.h>

// ---------------- problem constants (match dataset) ----------------
#define NMAXN 100000
#define EMAXE 1600000
#define HID 128
#define NOUT 10
#define BN_EPS 1e-5f
#define MAXSTATB 1024

// ---------------- static device scratch (alloc-free rule) ----------------
__device__ __align__(256) float g_bufA[(size_t)NMAXN * HID]; // BN+ReLU output
__device__ __align__(256) float g_bufB[(size_t)NMAXN * HID]; // gemm output
__device__ __align__(256) float g_bufC[(size_t)NMAXN * HID]; // aggregation output
__device__ __align__(256) int   g_cnt[NMAXN];
__device__ __align__(256) int   g_rowstart[NMAXN + 1];
__device__ __align__(256) int   g_cursor[NMAXN];
__device__ __align__(256) int   g_src_sorted[EMAXE];
__device__ __align__(256) float g_dinv[NMAXN];
__device__ __align__(256) float g_psum[(size_t)MAXSTATB * HID];
__device__ __align__(256) float g_psq [(size_t)MAXSTATB * HID];
__device__ __align__(256) float g_scale[HID];
__device__ __align__(256) float g_shift[HID];
__device__ __align__(256) int   g_partials[256];
__device__ __align__(256) int   g_partials_scan[256];
__device__ int g_is64;   // 1 if edge_index is int64, 0 if int32

// ---------------- dtype detection ----------------
// int64 nonneg small indices (little-endian): every odd 32-bit word is 0.
// int32 random indices in [0, 1e5): odd words are nonzero almost surely.
__global__ void k_detect(const unsigned int* __restrict__ raw) {
    __shared__ int any;
    if (threadIdx.x == 0) any = 0;
    __syncthreads();
    unsigned int w = raw[threadIdx.x * 2 + 1];   // odd words, first 512 words
    if (w != 0u) atomicOr(&any, 1);
    __syncthreads();
    if (threadIdx.x == 0) g_is64 = any ? 0 : 1;
}

// safe edge fetch (branches on detected dtype; clamps handled by caller)
__device__ __forceinline__ int edge_at(const void* ei, size_t idx) {
    if (g_is64) return (int)((const long long*)ei)[idx];
    return ((const int*)ei)[idx];
}

// ---------------- CSR build ----------------
__global__ void k_zero(int n) {
    int i = blockIdx.x * blockDim.x + threadIdx.x;
    if (i < n) { g_cnt[i] = 0; g_cursor[i] = 0; }
}

__global__ void k_count(const void* __restrict__ ei, int e, int n) {
    int i = blockIdx.x * blockDim.x + threadIdx.x;
    if (i < e) {
        int d = edge_at(ei, (size_t)e + i);
        if ((unsigned)d < (unsigned)n) atomicAdd(&g_cnt[d], 1);
    }
}

#define SCAN_B 1024
// per-block inclusive scan of counts; block totals to g_partials
__global__ void k_scan1(int n) {
    __shared__ int sh[SCAN_B];
    int i = blockIdx.x * SCAN_B + threadIdx.x;
    int v = (i < n) ? g_cnt[i] : 0;
    sh[threadIdx.x] = v;
    __syncthreads();
    for (int off = 1; off < SCAN_B; off <<= 1) {
        int t = 0;
        if ((int)threadIdx.x >= off) t = sh[threadIdx.x - off];
        __syncthreads();
        if ((int)threadIdx.x >= off) sh[threadIdx.x] += t;
        __syncthreads();
    }
    if (i < n) g_rowstart[i] = sh[threadIdx.x];          // local inclusive
    if (threadIdx.x == SCAN_B - 1) g_partials[blockIdx.x] = sh[SCAN_B - 1];
}

// single-block exclusive scan of block totals (nb <= 256)
__global__ void k_scan2(int nb) {
    __shared__ int sh[256];
    int v = ((int)threadIdx.x < nb) ? g_partials[threadIdx.x] : 0;
    sh[threadIdx.x] = v;
    __syncthreads();
    for (int off = 1; off < 256; off <<= 1) {
        int t = 0;
        if ((int)threadIdx.x >= off) t = sh[threadIdx.x - off];
        __syncthreads();
        if ((int)threadIdx.x >= off) sh[threadIdx.x] += t;
        __syncthreads();
    }
    g_partials_scan[threadIdx.x] = sh[threadIdx.x] - v;  // exclusive
}

// finalize: exclusive row starts + dinv (deg includes self-loop +1)
__global__ void k_scan3(int n) {
    int i = blockIdx.x * blockDim.x + threadIdx.x;
    if (i < n) {
        int cnt  = g_cnt[i];
        int incl = g_rowstart[i] + g_partials_scan[i / SCAN_B];
        g_rowstart[i] = incl - cnt;
        if (i == n - 1) g_rowstart[n] = incl;
        g_dinv[i] = rsqrtf((float)cnt + 1.0f);
    }
}

__global__ void k_bucket(const void* __restrict__ ei, int e, int n) {
    int i = blockIdx.x * blockDim.x + threadIdx.x;
    if (i < e) {
        int s = edge_at(ei, i);
        int d = edge_at(ei, (size_t)e + i);
        if ((unsigned)d < (unsigned)n && (unsigned)s < (unsigned)n) {
            int pos = atomicAdd(&g_cursor[d], 1);
            g_src_sorted[g_rowstart[d] + pos] = s;
        }
    }
}

// ---------------- SGEMM: [n,128] @ [128,128] -> g_bufB ----------------
#define GBM 64
#define GBK 16
#define GTM 4
#define GTN 8
__global__ __launch_bounds__(256) void k_gemm128(
    const float* __restrict__ Aext, int useExt,
    const float* __restrict__ W, int n)
{
    const float* A = useExt ? Aext : (const float*)g_bufA;
    __shared__ float As[GBM][GBK + 1];
    __shared__ float Ws[GBK][HID];
    int tid = threadIdx.x;
    int ty = tid >> 4;          // 0..15 -> 4 rows each
    int tx = tid & 15;          // 0..15 -> 8 cols (stride 16)
    int blockRow = blockIdx.x * GBM;

    float acc[GTM][GTN];
#pragma unroll
    for (int i = 0; i < GTM; i++)
#pragma unroll
        for (int j = 0; j < GTN; j++) acc[i][j] = 0.0f;

    for (int k0 = 0; k0 < HID; k0 += GBK) {
        for (int i = tid; i < GBM * GBK; i += 256) {
            int r = i / GBK, c = i % GBK;
            int gr = blockRow + r;
            As[r][c] = (gr < n) ? A[(size_t)gr * HID + k0 + c] : 0.0f;
        }
        for (int i = tid; i < GBK * HID; i += 256) {
            int r = i / HID, c = i % HID;
            Ws[r][c] = W[(size_t)(k0 + r) * HID + c];
        }
        __syncthreads();
#pragma unroll
        for (int k = 0; k < GBK; k++) {
            float a[GTM], b[GTN];
#pragma unroll
            for (int i = 0; i < GTM; i++) a[i] = As[ty * GTM + i][k];
#pragma unroll
            for (int j = 0; j < GTN; j++) b[j] = Ws[k][tx + j * 16];
#pragma unroll
            for (int i = 0; i < GTM; i++)
#pragma unroll
                for (int j = 0; j < GTN; j++) acc[i][j] += a[i] * b[j];
        }
        __syncthreads();
    }
#pragma unroll
    for (int i = 0; i < GTM; i++) {
        int gr = blockRow + ty * GTM + i;
        if (gr < n) {
#pragma unroll
            for (int j = 0; j < GTN; j++)
                g_bufB[(size_t)gr * HID + tx + j * 16] = acc[i][j];
        }
    }
}

// ---------------- small GEMM: g_bufA[n,128] @ W2[128,10] -> g_bufB[n,10] ----------------
__global__ __launch_bounds__(256) void k_gemm10(
    const float* __restrict__ W, int n)
{
    __shared__ float Ws[HID * NOUT];
    int tid = threadIdx.x;
    for (int i = tid; i < HID * NOUT; i += blockDim.x) Ws[i] = W[i];
    __syncthreads();
    int warp = tid >> 5, lane = tid & 31;
    int row = blockIdx.x * (blockDim.x >> 5) + warp;
    if (row >= n) return;
    const float* A = (const float*)g_bufA;
    float a0 = A[(size_t)row * HID + lane];
    float a1 = A[(size_t)row * HID + 32 + lane];
    float a2 = A[(size_t)row * HID + 64 + lane];
    float a3 = A[(size_t)row * HID + 96 + lane];
#pragma unroll
    for (int c = 0; c < NOUT; c++) {
        float p = a0 * Ws[lane * NOUT + c]
                + a1 * Ws[(lane + 32) * NOUT + c]
                + a2 * Ws[(lane + 64) * NOUT + c]
                + a3 * Ws[(lane + 96) * NOUT + c];
#pragma unroll
        for (int off = 16; off > 0; off >>= 1)
            p += __shfl_down_sync(0xffffffffu, p, off);
        if (lane == 0) g_bufB[(size_t)row * NOUT + c] = p;
    }
}

// ---------------- aggregation (GCN message passing), width 128 ----------------
// out[i] = dinv[i] * ( sum_{e: dst=i} dinv[src]*h[src] + dinv[i]*h[i] ) + bias
__global__ __launch_bounds__(256) void k_agg128(
    const float* __restrict__ bias, int n)
{
    int node = blockIdx.x * blockDim.y + threadIdx.y;
    if (node >= n) return;
    int lane = threadIdx.x; // 0..31, float4 per lane = 128 cols
    const float4* hp = (const float4*)g_bufB;
    float di = g_dinv[node];
    float4 v = hp[(size_t)node * 32 + lane];
    float4 acc;
    acc.x = di * v.x; acc.y = di * v.y; acc.z = di * v.z; acc.w = di * v.w;
    int beg = g_rowstart[node], end = g_rowstart[node + 1];
    for (int j = beg; j < end; j++) {
        int s = g_src_sorted[j];
        if ((unsigned)s >= (unsigned)n) continue;
        float w = g_dinv[s];
        float4 m = hp[(size_t)s * 32 + lane];
        acc.x += w * m.x; acc.y += w * m.y; acc.z += w * m.z; acc.w += w * m.w;
    }
    float4 bb = ((const float4*)bias)[lane];
    float4 o;
    o.x = di * acc.x + bb.x; o.y = di * acc.y + bb.y;
    o.z = di * acc.z + bb.z; o.w = di * acc.w + bb.w;
    ((float4*)g_bufC)[(size_t)node * 32 + lane] = o;
}

// width-10 variant (final layer): reads g_bufB[n,10], writes d_out
__global__ __launch_bounds__(256) void k_agg10(
    const float* __restrict__ bias, float* __restrict__ out, int n)
{
    int node = blockIdx.x * blockDim.y + threadIdx.y;
    if (node >= n) return;
    int lane = threadIdx.x;
    const float* h = (const float*)g_bufB;
    float di = g_dinv[node];
    float acc = 0.0f;
    if (lane < NOUT) acc = di * h[(size_t)node * NOUT + lane];
    int beg = g_rowstart[node], end = g_rowstart[node + 1];
    for (int j = beg; j < end; j++) {
        int s = g_src_sorted[j];
        if ((unsigned)s >= (unsigned)n) continue;
        float w = g_dinv[s];
        if (lane < NOUT) acc += w * h[(size_t)s * NOUT + lane];
    }
    if (lane < NOUT) out[(size_t)node * NOUT + lane] = di * acc + bias[lane];
}

// ---------------- BatchNorm stats: atomic-free two-stage reduction ----------------
__global__ __launch_bounds__(128) void k_stats(int n) {
    int c = threadIdx.x;                // column 0..127
    int r0 = blockIdx.x * 128;
    const float* x = (const float*)g_bufC;
    float s = 0.0f, q = 0.0f;
    int rend = r0 + 128; if (rend > n) rend = n;
    for (int r = r0; r < rend; r++) {
        float v = x[(size_t)r * HID + c];
        s += v; q += v * v;
    }
    g_psum[(size_t)blockIdx.x * HID + c] = s;
    g_psq [(size_t)blockIdx.x * HID + c] = q;
}

__global__ __launch_bounds__(128) void k_bnfinal(
    const float* __restrict__ g, const float* __restrict__ be,
    int nblocks, int n)
{
    int c = threadIdx.x;
    float s = 0.0f, q = 0.0f;
    for (int b = 0; b < nblocks; b++) {
        s += g_psum[(size_t)b * HID + c];
        q += g_psq [(size_t)b * HID + c];
    }
    float inv_n = 1.0f / (float)n;
    float mu  = s * inv_n;
    float var = fmaxf(q * inv_n - mu * mu, 0.0f);
    float sc = g[c] * rsqrtf(var + BN_EPS);
    g_scale[c] = sc;
    g_shift[c] = fmaf(-mu, sc, be[c]);
}

// BN apply + ReLU: reads g_bufC, writes g_bufA
__global__ __launch_bounds__(256) void k_bnrelu(int total)
{
    int idx = blockIdx.x * blockDim.x + threadIdx.x;
    if (idx < total) {
        int c = idx & (HID - 1);
        float v = fmaf(g_bufC[idx], g_scale[c], g_shift[c]);
        g_bufA[idx] = fmaxf(v, 0.0f);
    }
}

// ---------------- host launcher: kernel launches ONLY ----------------
extern "C" void kernel_launch(void* const* d_in, const int* in_sizes, int n_in,
                              void* d_out, int out_size)
{
    const float* x  = (const float*)d_in[0];
    const void*  ei = d_in[1];             // int32 or int64, detected on device
    const float* W0 = (const float*)d_in[2];  const float* b0 = (const float*)d_in[3];
    const float* g0 = (const float*)d_in[4];  const float* be0 = (const float*)d_in[5];
    const float* W1 = (const float*)d_in[6];  const float* b1 = (const float*)d_in[7];
    const float* g1 = (const float*)d_in[8];  const float* be1 = (const float*)d_in[9];
    const float* W2 = (const float*)d_in[10]; const float* b2 = (const float*)d_in[11];

    int n = in_sizes[0] / HID;
    int e = in_sizes[1] / 2;
    float* out = (float*)d_out;

    int nb_n256 = (n + 255) / 256;
    int nb_e256 = (e + 255) / 256;
    int nb_scan = (n + SCAN_B - 1) / SCAN_B;

    // ---- dtype probe + CSR build (per call; edge_index is an input) ----
    k_detect<<<1, 256>>>((const unsigned int*)ei);
    k_zero<<<nb_n256, 256>>>(n);
    k_count<<<nb_e256, 256>>>(ei, e, n);
    k_scan1<<<nb_scan, SCAN_B>>>(n);
    k_scan2<<<1, 256>>>(nb_scan);
    k_scan3<<<nb_n256, 256>>>(n);
    k_bucket<<<nb_e256, 256>>>(ei, e, n);

    dim3 aggBlk(32, 8);
    int aggGrid = (n + 7) / 8;
    int statGrid = (n + 127) / 128;   // <= MAXSTATB for n <= 131072
    int total = n * HID;
    int nb_t256 = (total + 255) / 256;
    int gemmGrid = (n + GBM - 1) / GBM;

    // ---- layer 0 ----
    k_gemm128<<<gemmGrid, 256>>>(x, 1, W0, n);
    k_agg128<<<aggGrid, aggBlk>>>(b0, n);
    k_stats<<<statGrid, 128>>>(n);
    k_bnfinal<<<1, 128>>>(g0, be0, statGrid, n);
    k_bnrelu<<<nb_t256, 256>>>(total);

    // ---- layer 1 ----
    k_gemm128<<<gemmGrid, 256>>>(x, 0, W1, n);
    k_agg128<<<aggGrid, aggBlk>>>(b1, n);
    k_stats<<<statGrid, 128>>>(n);
    k_bnfinal<<<1, 128>>>(g1, be1, statGrid, n);
    k_bnrelu<<<nb_t256, 256>>>(total);

    // ---- layer 2 (output) ----
    k_gemm10<<<(n + 7) / 8, 256>>>(W2, n);
    k_agg10<<<aggGrid, aggBlk>>>(b2, out, n);
}

// round 5
// speedup vs baseline: 1.3234x; 1.3234x over previous
#include <cuda_runtime.h>
#include <math.h>

// ---------------- problem constants (match dataset) ----------------
#define NMAXN 100000
#define EMAXE 1600000
#define HID 128
#define NOUT 10
#define BN_EPS 1e-5f

// ---------------- static device scratch (alloc-free rule) ----------------
__device__ __align__(256) float g_bufB[(size_t)NMAXN * HID]; // gemm output
__device__ __align__(256) float g_bufC[(size_t)NMAXN * HID]; // aggregation output
__device__ __align__(256) int   g_cnt[NMAXN];
__device__ __align__(256) int   g_rowstart[NMAXN + 1];
__device__ __align__(256) int   g_cursor[NMAXN];
__device__ __align__(256) int   g_src_sorted[EMAXE];
__device__ __align__(256) float g_dinv[NMAXN];
__device__ __align__(256) float g_cs[2][HID];   // per-layer column sums
__device__ __align__(256) float g_cq[2][HID];   // per-layer column sumsq
__device__ __align__(256) float g_scale[HID];
__device__ __align__(256) float g_shift[HID];
__device__ __align__(256) int   g_partials[256];
__device__ __align__(256) int   g_partials_scan[256];
__device__ int g_is64;   // 1 if edge_index is int64, 0 if int32

// ---------------- dtype detection ----------------
// int64 nonneg small indices (little-endian): every odd 32-bit word is 0.
// int32 random indices in [0, 1e5): odd words are nonzero almost surely.
__global__ void k_detect(const unsigned int* __restrict__ raw) {
    __shared__ int any;
    if (threadIdx.x == 0) any = 0;
    __syncthreads();
    unsigned int w = raw[threadIdx.x * 2 + 1];
    if (w != 0u) atomicOr(&any, 1);
    __syncthreads();
    if (threadIdx.x == 0) g_is64 = any ? 0 : 1;
}

__device__ __forceinline__ int edge_at(const void* ei, size_t idx) {
    if (g_is64) return (int)((const long long*)ei)[idx];
    return ((const int*)ei)[idx];
}

// ---------------- CSR build ----------------
__global__ void k_zero(int n) {
    int i = blockIdx.x * blockDim.x + threadIdx.x;
    if (i < n) { g_cnt[i] = 0; g_cursor[i] = 0; }
    if (i < HID) {
        g_cs[0][i] = 0.f; g_cq[0][i] = 0.f;
        g_cs[1][i] = 0.f; g_cq[1][i] = 0.f;
    }
}

__global__ void k_count(const void* __restrict__ ei, int e, int n) {
    int i = blockIdx.x * blockDim.x + threadIdx.x;
    if (i < e) {
        int d = edge_at(ei, (size_t)e + i);
        if ((unsigned)d < (unsigned)n) atomicAdd(&g_cnt[d], 1);
    }
}

#define SCAN_B 1024
__global__ void k_scan1(int n) {
    __shared__ int sh[SCAN_B];
    int i = blockIdx.x * SCAN_B + threadIdx.x;
    int v = (i < n) ? g_cnt[i] : 0;
    sh[threadIdx.x] = v;
    __syncthreads();
    for (int off = 1; off < SCAN_B; off <<= 1) {
        int t = 0;
        if ((int)threadIdx.x >= off) t = sh[threadIdx.x - off];
        __syncthreads();
        if ((int)threadIdx.x >= off) sh[threadIdx.x] += t;
        __syncthreads();
    }
    if (i < n) g_rowstart[i] = sh[threadIdx.x];
    if (threadIdx.x == SCAN_B - 1) g_partials[blockIdx.x] = sh[SCAN_B - 1];
}

__global__ void k_scan2(int nb) {
    __shared__ int sh[256];
    int v = ((int)threadIdx.x < nb) ? g_partials[threadIdx.x] : 0;
    sh[threadIdx.x] = v;
    __syncthreads();
    for (int off = 1; off < 256; off <<= 1) {
        int t = 0;
        if ((int)threadIdx.x >= off) t = sh[threadIdx.x - off];
        __syncthreads();
        if ((int)threadIdx.x >= off) sh[threadIdx.x] += t;
        __syncthreads();
    }
    g_partials_scan[threadIdx.x] = sh[threadIdx.x] - v;
}

__global__ void k_scan3(int n) {
    int i = blockIdx.x * blockDim.x + threadIdx.x;
    if (i < n) {
        int cnt  = g_cnt[i];
        int incl = g_rowstart[i] + g_partials_scan[i / SCAN_B];
        g_rowstart[i] = incl - cnt;
        if (i == n - 1) g_rowstart[n] = incl;
        g_dinv[i] = rsqrtf((float)cnt + 1.0f);
    }
}

__global__ void k_bucket(const void* __restrict__ ei, int e, int n) {
    int i = blockIdx.x * blockDim.x + threadIdx.x;
    if (i < e) {
        int s = edge_at(ei, i);
        int d = edge_at(ei, (size_t)e + i);
        if ((unsigned)d < (unsigned)n && (unsigned)s < (unsigned)n) {
            int pos = atomicAdd(&g_cursor[d], 1);
            g_src_sorted[g_rowstart[d] + pos] = s;
        }
    }
}

// ---------------- SGEMM: [n,128] @ [128,128] -> g_bufB ----------------
// 128x128 block tile, BK=16, 256 threads, 8x8 micro-tile.
// mode==0: A = Aext (layer-0 input x), plain.
// mode==1: A = relu(g_bufC * g_scale + g_shift)   (fused BN apply)
#define TBM 128
#define TBK 16
__global__ __launch_bounds__(256) void k_gemm128(
    const float* __restrict__ Aext, int mode,
    const float* __restrict__ W, int n)
{
    __shared__ float As[TBK][TBM + 4];
    __shared__ float Ws[TBK][HID];
    int tid = threadIdx.x;
    int tx = tid & 15;       // 0..15 -> col groups of 8
    int ty = tid >> 4;       // 0..15 -> row groups of 8
    int blockRow = blockIdx.x * TBM;
    const float* A = mode ? (const float*)g_bufC : Aext;

    float acc[8][8];
#pragma unroll
    for (int i = 0; i < 8; i++)
#pragma unroll
        for (int j = 0; j < 8; j++) acc[i][j] = 0.0f;

    for (int kb = 0; kb < HID; kb += TBK) {
        // ---- load A tile (128 x 16), transpose into As[k][row] ----
#pragma unroll
        for (int u = 0; u < 2; u++) {
            int idx = tid * 2 + u;          // 0..511
            int row = idx >> 2;             // 0..127
            int c4  = idx & 3;              // float4 within the 16-wide slab
            int gr  = blockRow + row;
            float4 v = make_float4(0.f, 0.f, 0.f, 0.f);
            if (gr < n) v = ((const float4*)A)[(size_t)gr * 32 + (kb >> 2) + c4];
            if (mode) {
                float4 sc = ((const float4*)g_scale)[(kb >> 2) + c4];
                float4 sh = ((const float4*)g_shift)[(kb >> 2) + c4];
                v.x = fmaxf(fmaf(v.x, sc.x, sh.x), 0.f);
                v.y = fmaxf(fmaf(v.y, sc.y, sh.y), 0.f);
                v.z = fmaxf(fmaf(v.z, sc.z, sh.z), 0.f);
                v.w = fmaxf(fmaf(v.w, sc.w, sh.w), 0.f);
            }
            int k0 = c4 * 4;
            As[k0 + 0][row] = v.x;
            As[k0 + 1][row] = v.y;
            As[k0 + 2][row] = v.z;
            As[k0 + 3][row] = v.w;
        }
        // ---- load W tile (16 x 128) row-major ----
#pragma unroll
        for (int u = 0; u < 2; u++) {
            int idx = tid * 2 + u;          // 0..511
            int r  = idx >> 5;              // 0..15
            int c4 = idx & 31;              // 0..31
            float4 v = ((const float4*)W)[(size_t)(kb + r) * 32 + c4];
            *(float4*)&Ws[r][c4 * 4] = v;
        }
        __syncthreads();
#pragma unroll
        for (int k = 0; k < TBK; k++) {
            float a[8], b[8];
            *(float4*)&a[0] = *(const float4*)&As[k][ty * 8];
            *(float4*)&a[4] = *(const float4*)&As[k][ty * 8 + 4];
            *(float4*)&b[0] = *(const float4*)&Ws[k][tx * 8];
            *(float4*)&b[4] = *(const float4*)&Ws[k][tx * 8 + 4];
#pragma unroll
            for (int i = 0; i < 8; i++)
#pragma unroll
                for (int j = 0; j < 8; j++)
                    acc[i][j] = fmaf(a[i], b[j], acc[i][j]);
        }
        __syncthreads();
    }
    // ---- store C ----
#pragma unroll
    for (int i = 0; i < 8; i++) {
        int gr = blockRow + ty * 8 + i;
        if (gr < n) {
            *(float4*)&g_bufB[(size_t)gr * HID + tx * 8]
                = make_float4(acc[i][0], acc[i][1], acc[i][2], acc[i][3]);
            *(float4*)&g_bufB[(size_t)gr * HID + tx * 8 + 4]
                = make_float4(acc[i][4], acc[i][5], acc[i][6], acc[i][7]);
        }
    }
}

// ---------------- small GEMM: relu(bn(g_bufC)) @ W2[128,10] -> g_bufB[n,10] ----------------
__global__ __launch_bounds__(256) void k_gemm10(
    const float* __restrict__ W, int n)
{
    __shared__ float Ws[HID * NOUT];
    int tid = threadIdx.x;
    for (int i = tid; i < HID * NOUT; i += blockDim.x) Ws[i] = W[i];
    __syncthreads();
    int warp = tid >> 5, lane = tid & 31;
    int row = blockIdx.x * (blockDim.x >> 5) + warp;
    if (row >= n) return;
    const float* A = (const float*)g_bufC;
    float a0 = fmaxf(fmaf(A[(size_t)row * HID + lane],      g_scale[lane],      g_shift[lane]),      0.f);
    float a1 = fmaxf(fmaf(A[(size_t)row * HID + 32 + lane], g_scale[lane + 32], g_shift[lane + 32]), 0.f);
    float a2 = fmaxf(fmaf(A[(size_t)row * HID + 64 + lane], g_scale[lane + 64], g_shift[lane + 64]), 0.f);
    float a3 = fmaxf(fmaf(A[(size_t)row * HID + 96 + lane], g_scale[lane + 96], g_shift[lane + 96]), 0.f);
#pragma unroll
    for (int c = 0; c < NOUT; c++) {
        float p = a0 * Ws[lane * NOUT + c]
                + a1 * Ws[(lane + 32) * NOUT + c]
                + a2 * Ws[(lane + 64) * NOUT + c]
                + a3 * Ws[(lane + 96) * NOUT + c];
#pragma unroll
        for (int off = 16; off > 0; off >>= 1)
            p += __shfl_down_sync(0xffffffffu, p, off);
        if (lane == 0) g_bufB[(size_t)row * NOUT + c] = p;
    }
}

// ---------------- aggregation + fused BN stats, width 128 ----------------
// reads g_bufB, writes g_bufC; accumulates column sum/sumsq into g_cs/g_cq[layer].
__global__ __launch_bounds__(256) void k_agg128(
    const float* __restrict__ bias, int n, int layer)
{
    __shared__ float shs[8][HID];
    __shared__ float shq[8][HID];
    int ty = threadIdx.y;
    int lane = threadIdx.x;
    int node = blockIdx.x * 8 + ty;
    bool active = node < n;
    const float4* hp = (const float4*)g_bufB;

    float4 o = make_float4(0.f, 0.f, 0.f, 0.f);
    if (active) {
        float di = g_dinv[node];
        float4 v = hp[(size_t)node * 32 + lane];
        float4 acc;
        acc.x = di * v.x; acc.y = di * v.y; acc.z = di * v.z; acc.w = di * v.w;
        int beg = g_rowstart[node], end = g_rowstart[node + 1];
        int j = beg;
        for (; j + 1 < end; j += 2) {
            int s0 = g_src_sorted[j];
            int s1 = g_src_sorted[j + 1];
            float w0 = g_dinv[s0];
            float w1 = g_dinv[s1];
            float4 m0 = hp[(size_t)s0 * 32 + lane];
            float4 m1 = hp[(size_t)s1 * 32 + lane];
            acc.x += w0 * m0.x + w1 * m1.x;
            acc.y += w0 * m0.y + w1 * m1.y;
            acc.z += w0 * m0.z + w1 * m1.z;
            acc.w += w0 * m0.w + w1 * m1.w;
        }
        if (j < end) {
            int s = g_src_sorted[j];
            float w = g_dinv[s];
            float4 m = hp[(size_t)s * 32 + lane];
            acc.x += w * m.x; acc.y += w * m.y; acc.z += w * m.z; acc.w += w * m.w;
        }
        float4 bb = ((const float4*)bias)[lane];
        o.x = fmaf(di, acc.x, bb.x); o.y = fmaf(di, acc.y, bb.y);
        o.z = fmaf(di, acc.z, bb.z); o.w = fmaf(di, acc.w, bb.w);
        ((float4*)g_bufC)[(size_t)node * 32 + lane] = o;
    }

    // fused BN statistics: block-local column reduction, then one atomic per column
    *(float4*)&shs[ty][lane * 4] = o;
    *(float4*)&shq[ty][lane * 4] = make_float4(o.x * o.x, o.y * o.y, o.z * o.z, o.w * o.w);
    __syncthreads();
    int tid = ty * 32 + lane;
    if (tid < HID) {
        float s = 0.f, q = 0.f;
#pragma unroll
        for (int r = 0; r < 8; r++) { s += shs[r][tid]; q += shq[r][tid]; }
        atomicAdd(&g_cs[layer][tid], s);
        atomicAdd(&g_cq[layer][tid], q);
    }
}

// width-10 variant (final layer): reads g_bufB[n,10], writes d_out
__global__ __launch_bounds__(256) void k_agg10(
    const float* __restrict__ bias, float* __restrict__ out, int n)
{
    int node = blockIdx.x * blockDim.y + threadIdx.y;
    if (node >= n) return;
    int lane = threadIdx.x;
    const float* h = (const float*)g_bufB;
    float di = g_dinv[node];
    float acc = 0.0f;
    if (lane < NOUT) acc = di * h[(size_t)node * NOUT + lane];
    int beg = g_rowstart[node], end = g_rowstart[node + 1];
    for (int j = beg; j < end; j++) {
        int s = g_src_sorted[j];
        if ((unsigned)s >= (unsigned)n) continue;
        float w = g_dinv[s];
        if (lane < NOUT) acc += w * h[(size_t)s * NOUT + lane];
    }
    if (lane < NOUT) out[(size_t)node * NOUT + lane] = di * acc + bias[lane];
}

// ---------------- BN finalize: scale/shift from accumulated stats ----------------
__global__ __launch_bounds__(128) void k_bnfinal(
    const float* __restrict__ g, const float* __restrict__ be,
    int layer, int n)
{
    int c = threadIdx.x;
    float inv_n = 1.0f / (float)n;
    float mu  = g_cs[layer][c] * inv_n;
    float var = fmaxf(g_cq[layer][c] * inv_n - mu * mu, 0.0f);
    float sc = g[c] * rsqrtf(var + BN_EPS);
    g_scale[c] = sc;
    g_shift[c] = fmaf(-mu, sc, be[c]);
}

// ---------------- host launcher: kernel launches ONLY ----------------
extern "C" void kernel_launch(void* const* d_in, const int* in_sizes, int n_in,
                              void* d_out, int out_size)
{
    const float* x  = (const float*)d_in[0];
    const void*  ei = d_in[1];             // int32 or int64, detected on device
    const float* W0 = (const float*)d_in[2];  const float* b0 = (const float*)d_in[3];
    const float* g0 = (const float*)d_in[4];  const float* be0 = (const float*)d_in[5];
    const float* W1 = (const float*)d_in[6];  const float* b1 = (const float*)d_in[7];
    const float* g1 = (const float*)d_in[8];  const float* be1 = (const float*)d_in[9];
    const float* W2 = (const float*)d_in[10]; const float* b2 = (const float*)d_in[11];

    int n = in_sizes[0] / HID;
    int e = in_sizes[1] / 2;
    float* out = (float*)d_out;

    int nb_n256 = (n + 255) / 256;
    int nb_e256 = (e + 255) / 256;
    int nb_scan = (n + SCAN_B - 1) / SCAN_B;

    // ---- dtype probe + CSR build ----
    k_detect<<<1, 256>>>((const unsigned int*)ei);
    k_zero<<<nb_n256, 256>>>(n);
    k_count<<<nb_e256, 256>>>(ei, e, n);
    k_scan1<<<nb_scan, SCAN_B>>>(n);
    k_scan2<<<1, 256>>>(nb_scan);
    k_scan3<<<nb_n256, 256>>>(n);
    k_bucket<<<nb_e256, 256>>>(ei, e, n);

    dim3 aggBlk(32, 8);
    int aggGrid = (n + 7) / 8;
    int gemmGrid = (n + TBM - 1) / TBM;

    // ---- layer 0 ----
    k_gemm128<<<gemmGrid, 256>>>(x, 0, W0, n);
    k_agg128<<<aggGrid, aggBlk>>>(b0, n, 0);
    k_bnfinal<<<1, 128>>>(g0, be0, 0, n);

    // ---- layer 1 (BN0 apply fused into A-load) ----
    k_gemm128<<<gemmGrid, 256>>>(x, 1, W1, n);
    k_agg128<<<aggGrid, aggBlk>>>(b1, n, 1);
    k_bnfinal<<<1, 128>>>(g1, be1, 1, n);

    // ---- layer 2 (BN1 apply fused into A-load; output) ----
    k_gemm10<<<(n + 7) / 8, 256>>>(W2, n);
    k_agg10<<<aggGrid, aggBlk>>>(b2, out, n);
}